// round 12
// baseline (speedup 1.0000x reference)
#include <cuda_runtime.h>
#include <cstdint>

// out[i, :] = embedding[index[i], :],  U=1M rows, D=64 f32 (256B/row), N=2M.
// Winning shape: 16 threads/row, one float4 each (row = 2 full 128B lines),
// UNROLL=4 front-batched independent gathers, exact straight-line grid cover.
// Single change vs best kernel: output stores use st.global.wt
// (write-THROUGH: no L2 allocation), so the 512MB write stream stops
// displacing embedding lines -> higher L2 hit rate on duplicate lookups ->
// less DRAM read traffic.
//   emb : __ldg  (L1+L2)
//   idx : __ldg  (L1 broadcast across the row's 16 lanes)
//   out : st.global.wt

static constexpr int UNROLL = 4;

__device__ __forceinline__ void stwt4(float4* p, float4 v) {
    asm volatile("st.global.wt.v4.f32 [%0], {%1,%2,%3,%4};"
                 :: "l"(p), "f"(v.x), "f"(v.y), "f"(v.z), "f"(v.w)
                 : "memory");
}

__global__ __launch_bounds__(256) void gather_kernel(
    const float4* __restrict__ emb,   // [U * 16] float4
    const int*    __restrict__ idx,   // [N]
    float4*       __restrict__ out,   // [N * 16] float4
    unsigned n_vec)                   // N * 16 = 2^25
{
    const unsigned stride = gridDim.x * blockDim.x;          // n_vec / 4
    const unsigned g0 = blockIdx.x * blockDim.x + threadIdx.x;

    if (g0 + 3u * stride < n_vec) {
        // Exact-cover fast path: straight-line 4 gathers.
        unsigned gg[UNROLL];
        int      src[UNROLL];
#pragma unroll
        for (int u = 0; u < UNROLL; u++) {
            gg[u] = g0 + u * stride;
            src[u] = __ldg(&idx[gg[u] >> 4]);
        }
        float4 v[UNROLL];
#pragma unroll
        for (int u = 0; u < UNROLL; u++) {
            unsigned seg = gg[u] & 15u;
            v[u] = __ldg(&emb[((int64_t)src[u] << 4) + seg]);
        }
#pragma unroll
        for (int u = 0; u < UNROLL; u++) {
            stwt4(&out[gg[u]], v[u]);
        }
    } else {
        // Generic tail (only if sizes aren't the expected exact fit).
        for (unsigned g = g0; g < n_vec; g += stride) {
            int src = __ldg(&idx[g >> 4]);
            unsigned seg = g & 15u;
            float4 v = __ldg(&emb[((int64_t)src << 4) + seg]);
            stwt4(&out[g], v);
        }
    }
}

extern "C" void kernel_launch(void* const* d_in, const int* in_sizes, int n_in,
                              void* d_out, int out_size) {
    const float4* emb = (const float4*)d_in[0];  // embedding [U, 64] f32
    const int*    idx = (const int*)d_in[1];     // index [N] i32
    float4*       out = (float4*)d_out;

    int64_t n = in_sizes[1];                     // N = 2097152
    unsigned n_vec = (unsigned)(n * 16);         // 33,554,432

    const int threads = 256;
    unsigned blocks = (n_vec + threads * UNROLL - 1) / (threads * UNROLL); // 32768
    gather_kernel<<<blocks, threads>>>(emb, idx, out, n_vec);
}

// round 13
// speedup vs baseline: 1.0134x; 1.0134x over previous
#include <cuda_runtime.h>
#include <cstdint>

// out[i, :] = embedding[index[i], :],  U=1M rows, D=64 f32 (256B/row), N=2M.
// Plateau configuration (all structural levers measured-dead; DRAM-efficiency
// bound at ~82% for mixed random-256B-read + streaming-write):
//   16 threads/row, one float4 each; UNROLL=4 front-batched gathers;
//   exact straight-line grid cover; block=512 (constant sweep).
//   emb : ld.global.cg  (best measured: R11, 149.8us)
//   idx : __ldg         (L1 broadcast across the row's 16 lanes)
//   out : __stcs        (evict-first streaming write)

static constexpr int UNROLL = 4;

__device__ __forceinline__ float4 ldcg4(const float4* p) {
    float4 v;
    asm("ld.global.cg.v4.f32 {%0,%1,%2,%3}, [%4];"
        : "=f"(v.x), "=f"(v.y), "=f"(v.z), "=f"(v.w)
        : "l"(p));
    return v;
}

__global__ __launch_bounds__(512) void gather_kernel(
    const float4* __restrict__ emb,   // [U * 16] float4
    const int*    __restrict__ idx,   // [N]
    float4*       __restrict__ out,   // [N * 16] float4
    unsigned n_vec)                   // N * 16 = 2^25
{
    const unsigned stride = gridDim.x * blockDim.x;          // n_vec / 4
    const unsigned g0 = blockIdx.x * blockDim.x + threadIdx.x;

    if (g0 + 3u * stride < n_vec) {
        // Exact-cover fast path: straight-line 4 independent gathers.
        unsigned gg[UNROLL];
        int      src[UNROLL];
#pragma unroll
        for (int u = 0; u < UNROLL; u++) {
            gg[u] = g0 + u * stride;
            src[u] = __ldg(&idx[gg[u] >> 4]);
        }
        float4 v[UNROLL];
#pragma unroll
        for (int u = 0; u < UNROLL; u++) {
            unsigned seg = gg[u] & 15u;
            v[u] = ldcg4(&emb[((int64_t)src[u] << 4) + seg]);
        }
#pragma unroll
        for (int u = 0; u < UNROLL; u++) {
            __stcs(&out[gg[u]], v[u]);
        }
    } else {
        // Generic tail (only if sizes aren't the expected exact fit).
        for (unsigned g = g0; g < n_vec; g += stride) {
            int src = __ldg(&idx[g >> 4]);
            unsigned seg = g & 15u;
            float4 v = ldcg4(&emb[((int64_t)src << 4) + seg]);
            __stcs(&out[g], v);
        }
    }
}

extern "C" void kernel_launch(void* const* d_in, const int* in_sizes, int n_in,
                              void* d_out, int out_size) {
    const float4* emb = (const float4*)d_in[0];  // embedding [U, 64] f32
    const int*    idx = (const int*)d_in[1];     // index [N] i32
    float4*       out = (float4*)d_out;

    int64_t n = in_sizes[1];                     // N = 2097152
    unsigned n_vec = (unsigned)(n * 16);         // 33,554,432

    const int threads = 512;
    unsigned blocks = (n_vec + threads * UNROLL - 1) / (threads * UNROLL); // 16384
    gather_kernel<<<blocks, threads>>>(emb, idx, out, n_vec);
}

// round 14
// speedup vs baseline: 1.0182x; 1.0047x over previous
#include <cuda_runtime.h>
#include <cstdint>

// out[i, :] = embedding[index[i], :],  U=1M rows, D=64 f32 (256B/row), N=2M.
// Winning shape (16 threads/row, one float4 each), deepened to UNROLL=8
// front-batched independent gathers: 256B of gather data in flight per
// thread to cover DRAM queueing latency at ~82% utilization.
//   emb : ld.global.cg  (L2-only; best measured)
//   idx : __ldg         (L1 broadcast across the row's 16 lanes)
//   out : __stcs        (evict-first streaming write)

static constexpr int UNROLL = 8;

__device__ __forceinline__ float4 ldcg4(const float4* p) {
    float4 v;
    asm("ld.global.cg.v4.f32 {%0,%1,%2,%3}, [%4];"
        : "=f"(v.x), "=f"(v.y), "=f"(v.z), "=f"(v.w)
        : "l"(p));
    return v;
}

__global__ __launch_bounds__(256) void gather_kernel(
    const float4* __restrict__ emb,   // [U * 16] float4
    const int*    __restrict__ idx,   // [N]
    float4*       __restrict__ out,   // [N * 16] float4
    unsigned n_vec)                   // N * 16 = 2^25
{
    const unsigned stride = gridDim.x * blockDim.x;          // n_vec / 8
    const unsigned g0 = blockIdx.x * blockDim.x + threadIdx.x;

    if (g0 + (UNROLL - 1) * stride < n_vec) {
        // Exact-cover fast path: straight-line 8 independent gathers.
        unsigned gg[UNROLL];
        int      src[UNROLL];
#pragma unroll
        for (int u = 0; u < UNROLL; u++) {
            gg[u] = g0 + u * stride;
            src[u] = __ldg(&idx[gg[u] >> 4]);
        }
        float4 v[UNROLL];
#pragma unroll
        for (int u = 0; u < UNROLL; u++) {
            unsigned seg = gg[u] & 15u;
            v[u] = ldcg4(&emb[((int64_t)src[u] << 4) + seg]);
        }
#pragma unroll
        for (int u = 0; u < UNROLL; u++) {
            __stcs(&out[gg[u]], v[u]);
        }
    } else {
        // Generic tail (only if sizes aren't the expected exact fit).
        for (unsigned g = g0; g < n_vec; g += stride) {
            int src = __ldg(&idx[g >> 4]);
            unsigned seg = g & 15u;
            float4 v = ldcg4(&emb[((int64_t)src << 4) + seg]);
            __stcs(&out[g], v);
        }
    }
}

extern "C" void kernel_launch(void* const* d_in, const int* in_sizes, int n_in,
                              void* d_out, int out_size) {
    const float4* emb = (const float4*)d_in[0];  // embedding [U, 64] f32
    const int*    idx = (const int*)d_in[1];     // index [N] i32
    float4*       out = (float4*)d_out;

    int64_t n = in_sizes[1];                     // N = 2097152
    unsigned n_vec = (unsigned)(n * 16);         // 33,554,432

    const int threads = 256;
    unsigned blocks = (n_vec + threads * UNROLL - 1) / (threads * UNROLL); // 16384
    gather_kernel<<<blocks, threads>>>(emb, idx, out, n_vec);
}